// round 13
// baseline (speedup 1.0000x reference)
#include <cuda_runtime.h>
#include <math.h>

#define BB 8
#define GG 16
#define PP 64
#define IMH 640
#define IMW 640
#define SZ 32
#define NITEMS (BB*PP*3)
#define NPBLOCKS (148*4)

// Gaussian window weights for WIN=11, sigma=1.5 (exp(-d^2/4.5), normalized),
// accurate to ~1e-8 vs the float64 reference; constexpr -> FFMA immediates.
__device__ constexpr float GW[6] = {
    0.26601172f,   // |d|=0
    0.21300554f,   // |d|=1
    0.10936070f,   // |d|=2
    0.03600077f,   // |d|=3
    0.00759876f,   // |d|=4
    0.00102838f    // |d|=5
};

__device__ double d_total = 0.0;
__device__ double d_cnt   = 0.0;
__device__ unsigned int d_done = 0;
__device__ unsigned int d_work = 0;

// Per-axis bilinear sampling coords, same arithmetic order as reference
__device__ __forceinline__ void axis_coord(float origin, float len, int maxdim, int i,
                                           int& lo, int& hi, float& wq) {
    float lm = fmaxf(len - 1.0f, 0.0f);
    float s  = fminf(fmaxf(((float)i + 0.5f) * (len / (float)SZ) - 0.5f, 0.0f), lm);
    float sf = floorf(s);
    wq = s - sf;
    float vlo = sf + origin;
    float vhi = fminf(sf + 1.0f, lm) + origin;
    lo = (int)fminf(fmaxf(vlo, 0.0f), (float)(maxdim - 1));
    hi = (int)fminf(fmaxf(vhi, 0.0f), (float)(maxdim - 1));
}

// Crop the two pixels (rows r0, r0+1; col=lane) of one box. Self-contained so
// its temporaries die before the conv loop (keeps hot-loop regs low).
__device__ __forceinline__ void crop_box(const float* __restrict__ imc,
                                         const float* __restrict__ box,
                                         int lane, int r0,
                                         float& v0, float& v1) {
    float bx = box[0], by = box[1], bw = box[2], bh = box[3];
    float x0 = floorf(bx), y0 = floorf(by);
    float w  = floorf(bx + bw) - x0;
    float h  = floorf(by + bh) - y0;
    int xlo, xhi, ylo0, yhi0, ylo1, yhi1;
    float wx, wy0, wy1;
    axis_coord(x0, w, IMW, lane, xlo, xhi, wx);
    axis_coord(y0, h, IMH, r0,   ylo0, yhi0, wy0);
    axis_coord(y0, h, IMH, r0+1, ylo1, yhi1, wy1);
    {
        int blo = ylo0*IMW, bhi = yhi0*IMW;
        float tl = __ldg(imc + blo + xlo);
        float tr = __ldg(imc + blo + xhi);
        float bl = __ldg(imc + bhi + xlo);
        float br = __ldg(imc + bhi + xhi);
        float top = tl*(1.0f-wx) + tr*wx;
        float bot = bl*(1.0f-wx) + br*wx;
        v0 = top*(1.0f-wy0) + bot*wy0;
    }
    {
        int blo = ylo1*IMW, bhi = yhi1*IMW;
        float tl = __ldg(imc + blo + xlo);
        float tr = __ldg(imc + blo + xhi);
        float bl = __ldg(imc + bhi + xlo);
        float br = __ldg(imc + bhi + xhi);
        float top = tl*(1.0f-wx) + tr*wx;
        float bot = bl*(1.0f-wx) + br*wx;
        v1 = top*(1.0f-wy1) + bot*wy1;
    }
}

// Warp-0-collective: pop one item and compute its 16-gt IoU ballot mask.
// Returns (item << 32) | mask.
__device__ __forceinline__ unsigned long long pop_item(const float* __restrict__ gt,
                                                       const float* __restrict__ pr,
                                                       int lane) {
    const unsigned FULL = 0xffffffffu;
    int item;
    if (lane == 0) item = (int)atomicAdd(&d_work, 1u);
    item = __shfl_sync(FULL, item, 0);
    bool pass = false;
    if (item < NITEMS && lane < GG) {
        int pi = item / 3;
        int b  = pi >> 6;
        int p  = pi & 63;
        const float* pb2 = pr + (size_t)(b*PP + p)*4;
        float px_ = pb2[0], py_ = pb2[1], pw_ = pb2[2], ph_ = pb2[3];
        const float* gb = gt + (size_t)(b*GG + lane)*4;
        float gx = gb[0], gy = gb[1], gw_ = gb[2], gh_ = gb[3];
        float tlx = fmaxf(gx - gw_*0.5f, px_ - pw_*0.5f);
        float tly = fmaxf(gy - gh_*0.5f, py_ - ph_*0.5f);
        float brx = fminf(gx + gw_*0.5f, px_ + pw_*0.5f);
        float bry = fminf(gy + gh_*0.5f, py_ + ph_*0.5f);
        float en  = ((tlx < brx) && (tly < bry)) ? 1.0f : 0.0f;
        float ai  = (brx - tlx) * (bry - tly) * en;
        float iou = ai / (gw_*gh_ + pw_*ph_ - ai + 1e-16f);
        pass = (iou > 0.3f) && (pw_ > 2.0f) && (ph_ > 2.0f);
    }
    unsigned msk = __ballot_sync(FULL, pass);
    return ((unsigned long long)(unsigned)item << 32) | (unsigned long long)msk;
}

// Padded H-field buffer: rows -5..36 (42 rows), index = (realrow+5)*32+lane.
// Pad rows are zero and never rewritten -> V-pass needs no row guards.
#define HROWS 42

__global__ void __launch_bounds__(512, 4)
fused_kernel(const float* __restrict__ gt,
             const float* __restrict__ pr,
             const float* __restrict__ imgs,
             float* __restrict__ out) {
    const unsigned FULL = 0xffffffffu;
    int t = threadIdx.x;
    int lane = t & 31;
    int warp = t >> 5;          // 0..15
    int r0 = warp * 2;          // warp owns rows r0, r0+1; lane owns col=lane

    __shared__ unsigned long long s_cur[2];   // parity-indexed (item, mask)
    __shared__ float4   Hb[2][HROWS*SZ];      // 4 fields, double-buffered, 43 KB
    __shared__ float    sred[16];
    __shared__ bool     s_last;

    // zero the pad rows (rows -5..-1 and 32..36) of both buffers, once per block
    if (t < 320) {
        int prow = t >> 5;                       // 0..9
        int row  = (prow < 5) ? prow : prow + 32;
        int k = row * SZ + (t & 31);
        float4 z = make_float4(0.0f, 0.0f, 0.0f, 0.0f);
        Hb[0][k] = z; Hb[1][k] = z;
    }
    // warp 0: pop the first item before the init barrier
    if (warp == 0) {
        unsigned long long pk = pop_item(gt, pr, lane);
        if (lane == 0) s_cur[0] = pk;
    }
    __syncthreads();

    const float C1 = 6.5025f;    // (0.01*255)^2
    const float C2 = 58.5225f;   // (0.03*255)^2
    float accf   = 0.0f;   // per-thread loss accumulator, carried across items
    int   cntloc = 0;      // masked-pair count (t==0 meaningful), c==0 items only
    int   it     = 0;      // item-slot parity
    int   gi     = 0;      // running gt-iteration counter -> Hb parity

    // ---- pipelined persistent work loop: items are (pred, channel) ----
    while (true) {
        unsigned long long pk = s_cur[it & 1];
        int      item = (int)(pk >> 32);
        unsigned mask = (unsigned)pk;
        if (item >= NITEMS) break;

        // prefetch NEXT item into the other slot; ordering to readers is
        // provided by the per-gt barrier below (nm>0) or the explicit one (nm==0)
        if (warp == 0) {
            unsigned long long nk = pop_item(gt, pr, lane);
            if (lane == 0) s_cur[(it + 1) & 1] = nk;
        }
        it++;

        int nm = __popc((int)mask);
        if (nm == 0) {
            __syncthreads();   // publish visible before next slot read
            continue;
        }

        int c  = item % 3;
        int pi = item / 3;
        int b  = pi >> 6;
        int p  = pi & 63;
        if (t == 0 && c == 0) cntloc += nm;

        const float* imc = imgs + ((size_t)b * 3 + c) * IMH * IMW;
        const float* pb  = pr + (size_t)(b*PP + p)*4;

        // pred crop: channel fixed per item -> hoist out of gt loop
        float x0v, x1v;
        crop_box(imc, pb, lane, r0, x0v, x1v);

        for (int m = 0; m < nm; m++, gi++) {
            int buf = gi & 1;                 // running parity across ALL items
            int g = __ffs((int)mask) - 1;
            mask &= mask - 1u;
            float y0v, y1v;
            crop_box(imc, gt + (size_t)(b*GG + g)*4, lane, r0, y0v, y1v);

            // sum/difference basis: s=x+y, dif=x-y.
            float s0 = x0v + y0v, e0 = x0v - y0v;
            float s1v = x1v + y1v, e1 = x1v - y1v;

            // L1 term: |x-y|/255, dif already available
            accf = fmaf(fabsf(e0), 1.0f/255.0f, accf);
            accf = fmaf(fabsf(e1), 1.0f/255.0f, accf);

            // horizontal pass via immediate-delta shuffles, zero-pad SAME.
            #pragma unroll
            for (int rr = 0; rr < 2; rr++) {
                float sv = rr ? s1v : s0;
                float ev = rr ? e1  : e0;
                float h0, h1, h2, h3;
                {   // d = 0
                    const float w0 = GW[0];
                    h0 = w0 * sv;
                    h1 = w0 * ev;
                    h2 = w0 * (sv*sv);
                    h3 = w0 * (ev*ev);
                }
                #pragma unroll
                for (int d = 1; d <= 5; d++) {
                    const float wv = GW[d];
                    float sp = __shfl_down_sync(FULL, sv, d);  // lane+d
                    float ep = __shfl_down_sync(FULL, ev, d);
                    float sm = __shfl_up_sync(FULL, sv, d);    // lane-d
                    float em = __shfl_up_sync(FULL, ev, d);
                    if (lane + d < 32) {
                        h0 = fmaf(wv, sp, h0);
                        h1 = fmaf(wv, ep, h1);
                        h2 = fmaf(wv, sp*sp, h2);
                        h3 = fmaf(wv, ep*ep, h3);
                    }
                    if (lane >= d) {
                        h0 = fmaf(wv, sm, h0);
                        h1 = fmaf(wv, em, h1);
                        h2 = fmaf(wv, sm*sm, h2);
                        h3 = fmaf(wv, em*em, h3);
                    }
                }
                int k = (r0 + rr + 5) * SZ + lane;   // padded row index
                Hb[buf][k] = make_float4(h0, h1, h2, h3);
            }
            __syncthreads();   // single barrier per gt (double buffer)

            // vertical pass over padded rows r0..r0+11, no guards (pads are zero)
            float v00=0.f,v01=0.f,v02=0.f,v03=0.f;
            float v10=0.f,v11=0.f,v12=0.f,v13=0.f;
            #pragma unroll
            for (int dd = 0; dd <= 11; dd++) {
                int k = (r0 + dd) * SZ + lane;
                float4 f = Hb[buf][k];
                if (dd <= 10) {                    // tap for output row r0
                    const float wv = GW[dd < 5 ? 5 - dd : dd - 5];
                    v00 = fmaf(wv, f.x, v00);
                    v01 = fmaf(wv, f.y, v01);
                    v02 = fmaf(wv, f.z, v02);
                    v03 = fmaf(wv, f.w, v03);
                }
                if (dd >= 1) {                     // tap for output row r0+1
                    const float wv = GW[dd < 6 ? 6 - dd : dd - 6];
                    v10 = fmaf(wv, f.x, v10);
                    v11 = fmaf(wv, f.y, v11);
                    v12 = fmaf(wv, f.z, v12);
                    v13 = fmaf(wv, f.w, v13);
                }
            }

            // SSIM in s/d basis. With S=conv(s), D=conv(dif), U=conv(s^2),
            // V=conv(dif^2):
            //   mu1^2+mu2^2 = (S^2+D^2)/2          mu12 = (S^2-D^2)/4
            //   s1+s2 = (U+V)/2 - (S^2+D^2)/2      s12  = (U-V)/4 - (S^2-D^2)/4
            {
                float S2 = v00*v00, D2 = v01*v01;
                float A = S2 + D2, B = S2 - D2;
                float sS  = 0.5f  * (v02 + v03 - A);
                float s12 = 0.25f * (v02 - v03 - B);
                float ssim = __fdividef((0.5f*B + C1) * (2.0f*s12 + C2),
                                        (0.5f*A + C1) * (sS + C2));
                accf += 1.0f - ssim;
            }
            {
                float S2 = v10*v10, D2 = v11*v11;
                float A = S2 + D2, B = S2 - D2;
                float sS  = 0.5f  * (v12 + v13 - A);
                float s12 = 0.25f * (v12 - v13 - B);
                float ssim = __fdividef((0.5f*B + C1) * (2.0f*s12 + C2),
                                        (0.5f*A + C1) * (sS + C2));
                accf += 1.0f - ssim;
            }
            // no trailing barrier: running parity alternates buffers, and the
            // next iteration's mid barrier separates read(j) from write(j+2)
        }
    }

    // ---- one block reduction at the end (16 warps) ----
    #pragma unroll
    for (int o = 16; o > 0; o >>= 1) accf += __shfl_down_sync(FULL, accf, o);
    if (lane == 0) sred[warp] = accf;
    __syncthreads();
    if (t < 16) {
        float v = sred[t];
        #pragma unroll
        for (int o = 8; o > 0; o >>= 1) v += __shfl_down_sync(0xffffu, v, o);
        if (t == 0) {
            if (v != 0.0f)  atomicAdd(&d_total, (double)v);
            if (cntloc > 0) atomicAdd(&d_cnt, (double)cntloc);
        }
    }

    // completion counter: last block finalizes and resets all globals
    __threadfence();
    if (t == 0) {
        unsigned prev = atomicAdd(&d_done, 1u);
        s_last = (prev == (unsigned)(NPBLOCKS - 1));
    }
    __syncthreads();
    if (s_last && t == 0) {
        double cnt = d_cnt * (double)(3*SZ*SZ);
        out[0] = (cnt > 0.0) ? (float)(d_total / fmax(cnt, 1.0)) : 0.0f;
        d_total = 0.0;
        d_cnt   = 0.0;
        d_done  = 0u;
        d_work  = 0u;
    }
}

extern "C" void kernel_launch(void* const* d_in, const int* in_sizes, int n_in,
                              void* d_out, int out_size) {
    const float* gt   = (const float*)d_in[0];
    const float* pr   = (const float*)d_in[1];
    const float* imgs = (const float*)d_in[2];
    float* out = (float*)d_out;

    fused_kernel<<<NPBLOCKS, 512>>>(gt, pr, imgs, out);
}

// round 14
// speedup vs baseline: 1.0118x; 1.0118x over previous
#include <cuda_runtime.h>
#include <math.h>

#define BB 8
#define GG 16
#define PP 64
#define IMH 640
#define IMW 640
#define SZ 32
#define NITEMS (BB*PP*3)
#define NPBLOCKS (148*4)

// Gaussian window weights for WIN=11, sigma=1.5 (exp(-d^2/4.5), normalized),
// accurate to ~1e-8 vs the float64 reference; constexpr -> FFMA immediates.
__device__ constexpr float GW[6] = {
    0.26601172f,   // |d|=0
    0.21300554f,   // |d|=1
    0.10936070f,   // |d|=2
    0.03600077f,   // |d|=3
    0.00759876f,   // |d|=4
    0.00102838f    // |d|=5
};

__device__ double d_total = 0.0;
__device__ double d_cnt   = 0.0;
__device__ unsigned int d_done = 0;
__device__ unsigned int d_work = 0;

// Per-axis bilinear sampling coords, same arithmetic order as reference
__device__ __forceinline__ void axis_coord(float origin, float len, int maxdim, int i,
                                           int& lo, int& hi, float& wq) {
    float lm = fmaxf(len - 1.0f, 0.0f);
    float s  = fminf(fmaxf(((float)i + 0.5f) * (len / (float)SZ) - 0.5f, 0.0f), lm);
    float sf = floorf(s);
    wq = s - sf;
    float vlo = sf + origin;
    float vhi = fminf(sf + 1.0f, lm) + origin;
    lo = (int)fminf(fmaxf(vlo, 0.0f), (float)(maxdim - 1));
    hi = (int)fminf(fmaxf(vhi, 0.0f), (float)(maxdim - 1));
}

// Crop the two pixels (rows r0, r0+1; col=lane) of one box. Self-contained so
// its temporaries die before the conv loop (keeps hot-loop regs low).
__device__ __forceinline__ void crop_box(const float* __restrict__ imc,
                                         const float* __restrict__ box,
                                         int lane, int r0,
                                         float& v0, float& v1) {
    float bx = box[0], by = box[1], bw = box[2], bh = box[3];
    float x0 = floorf(bx), y0 = floorf(by);
    float w  = floorf(bx + bw) - x0;
    float h  = floorf(by + bh) - y0;
    int xlo, xhi, ylo0, yhi0, ylo1, yhi1;
    float wx, wy0, wy1;
    axis_coord(x0, w, IMW, lane, xlo, xhi, wx);
    axis_coord(y0, h, IMH, r0,   ylo0, yhi0, wy0);
    axis_coord(y0, h, IMH, r0+1, ylo1, yhi1, wy1);
    {
        int blo = ylo0*IMW, bhi = yhi0*IMW;
        float tl = __ldg(imc + blo + xlo);
        float tr = __ldg(imc + blo + xhi);
        float bl = __ldg(imc + bhi + xlo);
        float br = __ldg(imc + bhi + xhi);
        float top = tl*(1.0f-wx) + tr*wx;
        float bot = bl*(1.0f-wx) + br*wx;
        v0 = top*(1.0f-wy0) + bot*wy0;
    }
    {
        int blo = ylo1*IMW, bhi = yhi1*IMW;
        float tl = __ldg(imc + blo + xlo);
        float tr = __ldg(imc + blo + xhi);
        float bl = __ldg(imc + bhi + xlo);
        float br = __ldg(imc + bhi + xhi);
        float top = tl*(1.0f-wx) + tr*wx;
        float bot = bl*(1.0f-wx) + br*wx;
        v1 = top*(1.0f-wy1) + bot*wy1;
    }
}

// Padded H-field buffer: rows -5..36 (42 rows), index = (realrow+5)*32+lane.
// Pad rows are zero and never rewritten -> V-pass needs no row guards.
#define HROWS 42

__global__ void __launch_bounds__(512, 4)
fused_kernel(const float* __restrict__ gt,
             const float* __restrict__ pr,
             const float* __restrict__ imgs,
             float* __restrict__ out) {
    const unsigned FULL = 0xffffffffu;
    int t = threadIdx.x;
    int lane = t & 31;
    int warp = t >> 5;          // 0..15
    int r0 = warp * 2;          // warp owns rows r0, r0+1; lane owns col=lane

    __shared__ int      s_item;
    __shared__ unsigned s_mask;
    __shared__ float4   Hb[2][HROWS*SZ];   // 4 fields packed, double-buffered, 43 KB
    __shared__ float    sred[16];
    __shared__ bool     s_last;

    // zero the pad rows (rows -5..-1 and 32..36) of both buffers, once per block
    if (t < 320) {
        int prow = t >> 5;                       // 0..9
        int row  = (prow < 5) ? prow : prow + 32;
        int k = row * SZ + (t & 31);
        float4 z = make_float4(0.0f, 0.0f, 0.0f, 0.0f);
        Hb[0][k] = z; Hb[1][k] = z;
    }

    const float C1 = 6.5025f;     // (0.01*255)^2
    const float C2 = 58.5225f;    // (0.03*255)^2
    const float C2x2 = 117.045f;  // 2*C2
    float accf   = 0.0f;   // per-thread loss accumulator, carried across items
    int   cntloc = 0;      // masked-pair count (t==0 meaningful), c==0 items only

    // ---- persistent work loop: items are (pred, channel) ----
    while (true) {
        // warp 0: pop next item and compute the 16-gt IoU mask via ballot
        if (warp == 0) {
            int item;
            if (lane == 0) item = (int)atomicAdd(&d_work, 1u);
            item = __shfl_sync(FULL, item, 0);
            bool pass = false;
            if (item < NITEMS && lane < GG) {
                int pi = item / 3;
                int b  = pi >> 6;
                int p  = pi & 63;
                const float* pb2 = pr + (size_t)(b*PP + p)*4;
                float px_ = pb2[0], py_ = pb2[1], pw_ = pb2[2], ph_ = pb2[3];
                const float* gb = gt + (size_t)(b*GG + lane)*4;
                float gx = gb[0], gy = gb[1], gw_ = gb[2], gh_ = gb[3];
                float tlx = fmaxf(gx - gw_*0.5f, px_ - pw_*0.5f);
                float tly = fmaxf(gy - gh_*0.5f, py_ - ph_*0.5f);
                float brx = fminf(gx + gw_*0.5f, px_ + pw_*0.5f);
                float bry = fminf(gy + gh_*0.5f, py_ + ph_*0.5f);
                float en  = ((tlx < brx) && (tly < bry)) ? 1.0f : 0.0f;
                float ai  = (brx - tlx) * (bry - tly) * en;
                float iou = ai / (gw_*gh_ + pw_*ph_ - ai + 1e-16f);
                pass = (iou > 0.3f) && (pw_ > 2.0f) && (ph_ > 2.0f);
            }
            unsigned msk = __ballot_sync(FULL, pass);
            if (lane == 0) { s_item = item; s_mask = msk; }
        }
        __syncthreads();                  // pop + mask visible to all
        int      item = s_item;
        unsigned mask = s_mask;
        if (item >= NITEMS) break;

        int nm = __popc((int)mask);
        if (nm == 0) {
            __syncthreads();              // all read s_item before next overwrite
            continue;
        }
        // for nm>0, the per-gt barrier below provides that separation

        int c  = item % 3;
        int pi = item / 3;
        int b  = pi >> 6;
        int p  = pi & 63;
        if (t == 0 && c == 0) cntloc += nm;

        const float* imc = imgs + ((size_t)b * 3 + c) * IMH * IMW;
        const float* pb  = pr + (size_t)(b*PP + p)*4;

        // pred crop: channel fixed per item -> hoist out of gt loop
        float x0v, x1v;
        crop_box(imc, pb, lane, r0, x0v, x1v);

        for (int m = 0; m < nm; m++) {
            int buf = m & 1;
            int g = __ffs((int)mask) - 1;
            mask &= mask - 1u;
            float y0v, y1v;
            crop_box(imc, gt + (size_t)(b*GG + g)*4, lane, r0, y0v, y1v);

            // sum/difference basis: s=x+y, dif=x-y.
            //   conv fields {s, dif, s^2, dif^2} recover everything SSIM needs.
            float s0 = x0v + y0v, e0 = x0v - y0v;
            float s1v = x1v + y1v, e1 = x1v - y1v;

            // L1 term: |x-y|/255, dif already available
            accf = fmaf(fabsf(e0), 1.0f/255.0f, accf);
            accf = fmaf(fabsf(e1), 1.0f/255.0f, accf);

            // horizontal pass via immediate-delta shuffles, zero-pad SAME.
            // center tap needs no shuffle; +/-d via shfl.down/shfl.up.
            #pragma unroll
            for (int rr = 0; rr < 2; rr++) {
                float sv = rr ? s1v : s0;
                float ev = rr ? e1  : e0;
                float h0, h1, h2, h3;
                {   // d = 0
                    const float w0 = GW[0];
                    h0 = w0 * sv;
                    h1 = w0 * ev;
                    h2 = w0 * (sv*sv);
                    h3 = w0 * (ev*ev);
                }
                #pragma unroll
                for (int d = 1; d <= 5; d++) {
                    const float wv = GW[d];
                    float sp = __shfl_down_sync(FULL, sv, d);  // lane+d
                    float ep = __shfl_down_sync(FULL, ev, d);
                    float sm = __shfl_up_sync(FULL, sv, d);    // lane-d
                    float em = __shfl_up_sync(FULL, ev, d);
                    if (lane + d < 32) {
                        h0 = fmaf(wv, sp, h0);
                        h1 = fmaf(wv, ep, h1);
                        h2 = fmaf(wv, sp*sp, h2);
                        h3 = fmaf(wv, ep*ep, h3);
                    }
                    if (lane >= d) {
                        h0 = fmaf(wv, sm, h0);
                        h1 = fmaf(wv, em, h1);
                        h2 = fmaf(wv, sm*sm, h2);
                        h3 = fmaf(wv, em*em, h3);
                    }
                }
                int k = (r0 + rr + 5) * SZ + lane;   // padded row index
                Hb[buf][k] = make_float4(h0, h1, h2, h3);
            }
            __syncthreads();   // single barrier per gt (double buffer)

            // vertical pass over padded rows r0..r0+11, no guards (pads are zero)
            float v00=0.f,v01=0.f,v02=0.f,v03=0.f;
            float v10=0.f,v11=0.f,v12=0.f,v13=0.f;
            #pragma unroll
            for (int dd = 0; dd <= 11; dd++) {
                int k = (r0 + dd) * SZ + lane;
                float4 f = Hb[buf][k];
                if (dd <= 10) {                    // tap for output row r0
                    const float wv = GW[dd < 5 ? 5 - dd : dd - 5];
                    v00 = fmaf(wv, f.x, v00);
                    v01 = fmaf(wv, f.y, v01);
                    v02 = fmaf(wv, f.z, v02);
                    v03 = fmaf(wv, f.w, v03);
                }
                if (dd >= 1) {                     // tap for output row r0+1
                    const float wv = GW[dd < 6 ? 6 - dd : dd - 6];
                    v10 = fmaf(wv, f.x, v10);
                    v11 = fmaf(wv, f.y, v11);
                    v12 = fmaf(wv, f.z, v12);
                    v13 = fmaf(wv, f.w, v13);
                }
            }

            // SSIM in s/d basis, constants folded. With S=conv(s), D=conv(dif),
            // U=conv(s^2), V=conv(dif^2), A=S^2+D^2, B=S^2-D^2:
            //   ssim = ((B/2+C1)(U-V-B+2C2)) / ((A/2+C1)(U+V-A+2C2))
            // (the 1/2 factors of numerator/denominator second terms cancel)
            {
                float S2 = v00*v00, D2 = v01*v01;
                float A = S2 + D2, B = S2 - D2;
                float ssim = __fdividef((fmaf(0.5f, B, C1)) * (v02 - v03 - B + C2x2),
                                        (fmaf(0.5f, A, C1)) * (v02 + v03 - A + C2x2));
                accf += 1.0f - ssim;
            }
            {
                float S2 = v10*v10, D2 = v11*v11;
                float A = S2 + D2, B = S2 - D2;
                float ssim = __fdividef((fmaf(0.5f, B, C1)) * (v12 - v13 - B + C2x2),
                                        (fmaf(0.5f, A, C1)) * (v12 + v13 - A + C2x2));
                accf += 1.0f - ssim;
            }
            // no trailing barrier: next gt writes the other buffer
        }
    }

    // ---- one block reduction at the end (16 warps) ----
    #pragma unroll
    for (int o = 16; o > 0; o >>= 1) accf += __shfl_down_sync(FULL, accf, o);
    if (lane == 0) sred[warp] = accf;
    __syncthreads();
    if (t < 16) {
        float v = sred[t];
        #pragma unroll
        for (int o = 8; o > 0; o >>= 1) v += __shfl_down_sync(0xffffu, v, o);
        if (t == 0) {
            if (v != 0.0f)  atomicAdd(&d_total, (double)v);
            if (cntloc > 0) atomicAdd(&d_cnt, (double)cntloc);
        }
    }

    // completion counter: last block finalizes and resets all globals
    __threadfence();
    if (t == 0) {
        unsigned prev = atomicAdd(&d_done, 1u);
        s_last = (prev == (unsigned)(NPBLOCKS - 1));
    }
    __syncthreads();
    if (s_last && t == 0) {
        double cnt = d_cnt * (double)(3*SZ*SZ);
        out[0] = (cnt > 0.0) ? (float)(d_total / fmax(cnt, 1.0)) : 0.0f;
        d_total = 0.0;
        d_cnt   = 0.0;
        d_done  = 0u;
        d_work  = 0u;
    }
}

extern "C" void kernel_launch(void* const* d_in, const int* in_sizes, int n_in,
                              void* d_out, int out_size) {
    const float* gt   = (const float*)d_in[0];
    const float* pr   = (const float*)d_in[1];
    const float* imgs = (const float*)d_in[2];
    float* out = (float*)d_out;

    fused_kernel<<<NPBLOCKS, 512>>>(gt, pr, imgs, out);
}